// round 17
// baseline (speedup 1.0000x reference)
#include <cuda_runtime.h>
#include <cuda_fp16.h>
#include <stdint.h>
#include <math.h>

#define N_TOK 32768
#define DIMX  512
#define HID   2048
#define NEXP  16
#define MAXTILE 272   // sum ceil(Me/128) <= 256 + 16

// ---------------- scratch (static device globals; no runtime allocation) ----
__device__ int g_leaf[N_TOK];
__device__ int g_cnt[NEXP];
__device__ int g_off[NEXP + 1];
__device__ int g_cur[NEXP];
__device__ int g_perm[N_TOK];
__device__ int g_tmap_e[MAXTILE];
__device__ int g_tmap_m[MAXTILE];
__device__ int g_ntile;

__device__ __half g_xh[(size_t)N_TOK * DIMX];
__device__ __half g_w1h[(size_t)NEXP * DIMX * HID];  // transposed [E][HID][DIMX]
__device__ __half g_w2h[(size_t)NEXP * DIMX * HID];  // transposed [E][DIMX][HID]
__device__ __half g_hh[(size_t)N_TOK * HID];

// ---------------- routing (exact fp32) + fused x cast ------------------------
__global__ void k_zero() {
    if (threadIdx.x < NEXP) g_cnt[threadIdx.x] = 0;
}

__global__ void k_route(const float* __restrict__ x,
                        const float* __restrict__ Wr,
                        const float* __restrict__ br,
                        __half* __restrict__ xh) {
    int warp = (blockIdx.x * blockDim.x + threadIdx.x) >> 5;
    int lane = threadIdx.x & 31;
    const float4* xp = (const float4*)(x + (size_t)warp * DIMX);
    float4 xr[4];
#pragma unroll
    for (int j = 0; j < 4; j++) xr[j] = xp[lane + 32 * j];

    // fused fp16 cast (same data already in registers)
    __half* xhp = xh + (size_t)warp * DIMX;
#pragma unroll
    for (int j = 0; j < 4; j++) {
        __half2 a = __floats2half2_rn(xr[j].x, xr[j].y);
        __half2 b = __floats2half2_rn(xr[j].z, xr[j].w);
        *(__half2*)(xhp + (lane + 32 * j) * 4)     = a;
        *(__half2*)(xhp + (lane + 32 * j) * 4 + 2) = b;
    }

    int leaf = 0;
#pragma unroll
    for (int d = 0; d < 4; d++) {
        int r = (1 << d) - 1 + leaf;
        const float4* wp = (const float4*)(Wr + (size_t)r * DIMX);
        float s = 0.f;
#pragma unroll
        for (int j = 0; j < 4; j++) {
            float4 w = wp[lane + 32 * j];
            s += xr[j].x * w.x; s += xr[j].y * w.y;
            s += xr[j].z * w.z; s += xr[j].w * w.w;
        }
#pragma unroll
        for (int o = 16; o; o >>= 1) s += __shfl_xor_sync(0xffffffffu, s, o);
        leaf = leaf * 2 + (((s + br[r]) > 0.f) ? 1 : 0);
    }
    if (lane == 0) {
        g_leaf[warp] = leaf;
        atomicAdd(&g_cnt[leaf], 1);
    }
}

// prefix + tile map (sum of ceil(Me/128) tiles, no empty-expert fat)
__global__ void k_prefix() {
    int acc = 0, t = 0;
    for (int e = 0; e < NEXP; e++) {
        g_off[e] = acc;
        g_cur[e] = acc;
        int c = g_cnt[e];
        for (int m = 0; m < c; m += 128) {
            g_tmap_e[t] = e;
            g_tmap_m[t] = m;
            t++;
        }
        acc += c;
    }
    g_off[NEXP] = acc;
    g_ntile = t;
    for (int i = t; i < MAXTILE; i++) { g_tmap_e[i] = -1; g_tmap_m[i] = 0; }
}

__global__ void k_scatter() {
    int n = blockIdx.x * blockDim.x + threadIdx.x;
    int pos = atomicAdd(&g_cur[g_leaf[n]], 1);
    g_perm[pos] = n;
}

// ---------------- W cast: [E][K][N] -> transposed fp16 [E][N][K] --------------
__global__ void k_cast_wT(const float* __restrict__ W,
                          __half* __restrict__ Th,
                          int K, int N) {
    __shared__ float s[32][33];
    int e  = blockIdx.z;
    int k0 = blockIdx.y * 32;
    int n0 = blockIdx.x * 32;
    int tx = threadIdx.x, ty = threadIdx.y;
    const float* Wp = W + (size_t)e * K * N;
#pragma unroll
    for (int i = 0; i < 4; i++)
        s[ty + i * 8][tx] = Wp[(size_t)(k0 + ty + i * 8) * N + n0 + tx];
    __syncthreads();
    __half* ThP = Th + (size_t)e * N * K;
#pragma unroll
    for (int i = 0; i < 4; i++) {
        int rn = ty + i * 8;
        ThP[(size_t)(n0 + rn) * K + k0 + tx] = __float2half_rn(s[tx][rn]);
    }
}

// ---------------- mma / ldmatrix / cp.async ----------------------------------
__device__ __forceinline__ void mma_f16_f32(float* c, const uint32_t* a, const uint32_t* b) {
    asm volatile(
        "mma.sync.aligned.m16n8k16.row.col.f32.f16.f16.f32 "
        "{%0,%1,%2,%3}, {%4,%5,%6,%7}, {%8,%9}, {%0,%1,%2,%3};"
        : "+f"(c[0]), "+f"(c[1]), "+f"(c[2]), "+f"(c[3])
        : "r"(a[0]), "r"(a[1]), "r"(a[2]), "r"(a[3]), "r"(b[0]), "r"(b[1]));
}

__device__ __forceinline__ void ldm_x4(uint32_t* r, uint32_t addr) {
    asm volatile("ldmatrix.sync.aligned.m8n8.x4.shared.b16 {%0,%1,%2,%3}, [%4];"
                 : "=r"(r[0]), "=r"(r[1]), "=r"(r[2]), "=r"(r[3]) : "r"(addr));
}

__device__ __forceinline__ void cp16(uint32_t smem_dst, const void* gmem_src) {
    asm volatile("cp.async.cg.shared.global [%0], [%1], 16;" :: "r"(smem_dst), "l"(gmem_src));
}

// ---------------- grouped GEMM (pure fp16, 128x128 tile, 512 thr) ------------
// D = A@B^T, fp32 accum. BM=BN=128, BK=64, 4-stage cp.async ring,
// next-stage load issued BEFORE compute. 16 warps 4(M)x4(N), warp 32x32.
#define ROWP 72
#define TILE_H (128 * ROWP)              // halves per 128-row tile
#define STG_B  (2 * TILE_H * 2)          // bytes per stage (A + B)
#define NSTG   4
#define GEMM_SMEM (NSTG * STG_B)         // 147456 bytes

template<int KDIM, int NDIM, bool FFN1>
__global__ __launch_bounds__(512, 1)
void k_gemm(const __half* __restrict__ A_g,
            const __half* __restrict__ B_g,
            const float* __restrict__ bias,
            __half* __restrict__ Dh,
            float* __restrict__ Dout) {
    const int t = blockIdx.y;
    const int e = g_tmap_e[t];
    if (e < 0) return;
    const int M    = g_cnt[e];
    const int m0   = g_tmap_m[t];
    const int n0   = blockIdx.x * 128;
    const int tid  = threadIdx.x;
    const int lane = tid & 31;
    const int wm   = (tid >> 5) >> 2;    // 0..3
    const int wn   = (tid >> 5) & 3;     // 0..3
    const int ooff = g_off[e];

    extern __shared__ __half sm[];
    const uint32_t smb = (uint32_t)__cvta_generic_to_shared(sm);
    auto aOff = [&](int s) { return smb + (uint32_t)(s * STG_B); };
    auto bOff = [&](int s) { return smb + (uint32_t)(s * STG_B + TILE_H * 2); };

    // ---- producers: 512 threads; row = tid>>2, two 16B chunks per buffer ----
    const int prow = tid >> 2;           // 0..127
    const int pc   = (tid & 3) * 2;      // chunk pair base (16B units)
    const bool aval = (m0 + prow) < M;
    size_t arow_idx;
    if (FFN1) arow_idx = (size_t)(aval ? g_perm[ooff + m0 + prow] : 0);
    else      arow_idx = (size_t)(aval ? (ooff + m0 + prow) : 0);
    const __half* aph = A_g + arow_idx * KDIM;
    const __half* bph = B_g + ((size_t)e * NDIM + n0 + prow) * KDIM;

    auto load_stage = [&](int s, int ke) {
        const uint32_t d = prow * ROWP * 2;
#pragma unroll
        for (int c = 0; c < 2; c++) {
            cp16(aOff(s) + d + (pc + c) * 16, aph + ke + (pc + c) * 8);
            cp16(bOff(s) + d + (pc + c) * 16, bph + ke + (pc + c) * 8);
        }
        asm volatile("cp.async.commit_group;");
    };

    float acc[2][4][4];
#pragma unroll
    for (int mt = 0; mt < 2; mt++)
#pragma unroll
        for (int nt = 0; nt < 4; nt++)
#pragma unroll
            for (int i = 0; i < 4; i++) acc[mt][nt][i] = 0.f;

    constexpr int NCH = KDIM / 64;
    load_stage(0, 0);
    load_stage(1, 64);
    load_stage(2, 128);

    // ldmatrix lane geometry
    const int arr = wm * 32 + (lane & 15);                      // + mt*16
    const int acl = (lane >> 4) << 3;                           // 0 or 8
    const int bnr = wn * 32 + (lane & 7) + ((lane >> 4) << 3);  // + ntp*16
    const int bcl = lane & 8;                                   // 0 or 8

    for (int ch = 0; ch < NCH; ch++) {
        const int s   = ch & (NSTG - 1);
        const int rem = NCH - 1 - ch;      // groups pending beyond ch (pre-issue)
        if (rem >= 2)      asm volatile("cp.async.wait_group 2;");
        else if (rem == 1) asm volatile("cp.async.wait_group 1;");
        else               asm volatile("cp.async.wait_group 0;");
        __syncthreads();

        // issue next stage BEFORE compute (slot (ch+3)&3 is free in 4-ring)
        if (ch + 3 < NCH) load_stage((ch + 3) & (NSTG - 1), (ch + 3) * 64);

#pragma unroll
        for (int ks = 0; ks < 4; ks++) {
            const int wb = ks * 16;
            uint32_t Af[2][4], Bf[4][2];
#pragma unroll
            for (int mt = 0; mt < 2; mt++) {
                uint32_t ra = (uint32_t)(((arr + mt * 16) * ROWP + wb + acl) * 2);
                ldm_x4(Af[mt], aOff(s) + ra);
            }
#pragma unroll
            for (int ntp = 0; ntp < 2; ntp++) {
                uint32_t rb = (uint32_t)(((bnr + ntp * 16) * ROWP + wb + bcl) * 2);
                uint32_t rr[4];
                ldm_x4(rr, bOff(s) + rb);
                Bf[2 * ntp][0]     = rr[0];
                Bf[2 * ntp][1]     = rr[1];
                Bf[2 * ntp + 1][0] = rr[2];
                Bf[2 * ntp + 1][1] = rr[3];
            }
#pragma unroll
            for (int mt = 0; mt < 2; mt++)
#pragma unroll
                for (int nt = 0; nt < 4; nt++)
                    mma_f16_f32(acc[mt][nt], Af[mt], Bf[nt]);
        }
        __syncthreads();
    }

    // ---- epilogue ----
    const float* bp = bias + (size_t)e * NDIM;
    const int gl = lane >> 2, tl = lane & 3;
#pragma unroll
    for (int mt = 0; mt < 2; mt++) {
#pragma unroll
        for (int half = 0; half < 2; half++) {
            int row = wm * 32 + mt * 16 + gl + half * 8;
            if (m0 + row < M) {
#pragma unroll
                for (int nt = 0; nt < 4; nt++) {
                    int col = n0 + wn * 32 + nt * 8 + 2 * tl;
                    float v0 = acc[mt][nt][half * 2 + 0] + bp[col];
                    float v1 = acc[mt][nt][half * 2 + 1] + bp[col + 1];
                    if (FFN1) {
                        v0 = 0.5f * v0 * (1.f + erff(v0 * 0.7071067811865476f));
                        v1 = 0.5f * v1 * (1.f + erff(v1 * 0.7071067811865476f));
                        size_t drow = (size_t)(ooff + m0 + row);
                        *(__half2*)(Dh + drow * NDIM + col) = __floats2half2_rn(v0, v1);
                    } else {
                        size_t drow = (size_t)g_perm[ooff + m0 + row];
                        *(float2*)(Dout + drow * NDIM + col) = make_float2(v0, v1);
                    }
                }
            }
        }
    }
}

// ---------------- launch -----------------------------------------------------
extern "C" void kernel_launch(void* const* d_in, const int* in_sizes, int n_in,
                              void* d_out, int out_size) {
    const float* x  = (const float*)d_in[0];
    const float* Wr = (const float*)d_in[1];
    const float* br = (const float*)d_in[2];
    const float* W1 = (const float*)d_in[3];
    const float* b1 = (const float*)d_in[4];
    const float* W2 = (const float*)d_in[5];
    const float* b2 = (const float*)d_in[6];
    float* out = (float*)d_out;

    __half *xh, *w1h, *w2h, *hh;
    cudaGetSymbolAddress((void**)&xh,  g_xh);
    cudaGetSymbolAddress((void**)&w1h, g_w1h);
    cudaGetSymbolAddress((void**)&w2h, g_w2h);
    cudaGetSymbolAddress((void**)&hh,  g_hh);

    cudaFuncSetAttribute(k_gemm<DIMX, HID, true>,
                         cudaFuncAttributeMaxDynamicSharedMemorySize, GEMM_SMEM);
    cudaFuncSetAttribute(k_gemm<HID, DIMX, false>,
                         cudaFuncAttributeMaxDynamicSharedMemorySize, GEMM_SMEM);

    k_zero<<<1, 32>>>();
    k_route<<<N_TOK / 8, 256>>>(x, Wr, br, xh);   // route + fused x->fp16 cast
    k_prefix<<<1, 1>>>();
    k_scatter<<<N_TOK / 256, 256>>>();

    k_cast_wT<<<dim3(HID / 32, DIMX / 32, NEXP), dim3(32, 8)>>>(W1, w1h, DIMX, HID);
    k_cast_wT<<<dim3(DIMX / 32, HID / 32, NEXP), dim3(32, 8)>>>(W2, w2h, HID, DIMX);

    k_gemm<DIMX, HID, true ><<<dim3(HID / 128, MAXTILE, 1), 512, GEMM_SMEM>>>(
        xh, w1h, b1, hh, nullptr);
    k_gemm<HID, DIMX, false><<<dim3(DIMX / 128, MAXTILE, 1), 512, GEMM_SMEM>>>(
        hh, w2h, b2, nullptr, out);
}